// round 2
// baseline (speedup 1.0000x reference)
#include <cuda_runtime.h>
#include <math.h>

#define Bd 4
#define Sd 1024
#define Dd 1024
#define Hd 16
#define DKd 64
#define DFFd 4096
#define Md (Bd * Sd)   // 4096 rows

// ---------------- scratch (device globals; no runtime allocation) ----------
__device__ float g_xn [Md * Dd];
__device__ float g_q  [Md * Dd];
__device__ float g_k  [Md * Dd];
__device__ float g_v  [Md * Dd];
__device__ float g_ctx[Md * Dd];
__device__ float g_x2 [Md * Dd];
__device__ float g_xn2[Md * Dd];
__device__ float g_ff [Md * DFFd];

// ---------------- LayerNorm (torch-style: ddof=1, eps on std) --------------
__global__ void ln_kernel(const float* __restrict__ X, float* __restrict__ Y,
                          const float* __restrict__ alpha,
                          const float* __restrict__ beta) {
    __shared__ float red[256];
    __shared__ float s_mean, s_inv;
    const int row = blockIdx.x;
    const int tid = threadIdx.x;
    const float* x = X + (size_t)row * Dd;

    // each thread owns exactly one float4 (1024 / 256 = 4)
    float4 xv = *(const float4*)(x + tid * 4);
    float s = xv.x + xv.y + xv.z + xv.w;
    red[tid] = s; __syncthreads();
    #pragma unroll
    for (int off = 128; off > 0; off >>= 1) {
        if (tid < off) red[tid] += red[tid + off];
        __syncthreads();
    }
    if (tid == 0) s_mean = red[0] * (1.0f / Dd);
    __syncthreads();
    const float mean = s_mean;
    float dx = xv.x - mean, dy = xv.y - mean, dz = xv.z - mean, dw = xv.w - mean;
    float ss = dx * dx + dy * dy + dz * dz + dw * dw;
    red[tid] = ss; __syncthreads();
    #pragma unroll
    for (int off = 128; off > 0; off >>= 1) {
        if (tid < off) red[tid] += red[tid + off];
        __syncthreads();
    }
    if (tid == 0) {
        float var = red[0] * (1.0f / (Dd - 1));
        s_inv = alpha[0] / (sqrtf(var) + 1e-6f);
    }
    __syncthreads();
    const float inv = s_inv;
    const float bt  = beta[0];
    float4 o;
    o.x = dx * inv + bt; o.y = dy * inv + bt;
    o.z = dz * inv + bt; o.w = dw * inv + bt;
    *(float4*)(Y + (size_t)row * Dd + tid * 4) = o;
}

// ---------------- SGEMM 128x128x8, double-buffered, 8x8 per thread ---------
// C[M,N] = A[M,K] @ B[K,N] + bias[N]  (optional relu, optional residual add)
template <bool RELU, bool RES>
__global__ void __launch_bounds__(256, 2)
sgemm128(const float* __restrict__ A, const float* __restrict__ Bm,
         const float* __restrict__ bias, const float* __restrict__ Rm,
         float* __restrict__ C, int M, int N, int K) {
    __shared__ float As[2][8][128];
    __shared__ float Bs[2][8][128];

    const int tid = threadIdx.x;
    const int tx = tid & 15;        // 0..15 -> 8 cols each
    const int ty = tid >> 4;        // 0..15 -> 8 rows each
    const int m0 = blockIdx.y * 128;
    const int n0 = blockIdx.x * 128;

    const int arow = tid >> 1;            // 0..127
    const int acol = (tid & 1) * 4;       // 0 or 4
    const int brow = tid >> 5;            // 0..7
    const int bcol = (tid & 31) * 4;      // 0..124

    const float* Aptr = A + (size_t)(m0 + arow) * K + acol;
    const float* Bptr = Bm + (size_t)brow * N + n0 + bcol;

    float4 aReg = *(const float4*)Aptr;
    float4 bReg = *(const float4*)Bptr;

    float acc[8][8];
    #pragma unroll
    for (int i = 0; i < 8; i++)
        #pragma unroll
        for (int j = 0; j < 8; j++) acc[i][j] = 0.f;

    const int nt = K >> 3;
    int buf = 0;
    for (int t = 0; t < nt; t++) {
        As[buf][acol + 0][arow] = aReg.x;
        As[buf][acol + 1][arow] = aReg.y;
        As[buf][acol + 2][arow] = aReg.z;
        As[buf][acol + 3][arow] = aReg.w;
        *(float4*)&Bs[buf][brow][bcol] = bReg;
        __syncthreads();
        if (t + 1 < nt) {
            aReg = *(const float4*)(Aptr + (size_t)(t + 1) * 8);
            bReg = *(const float4*)(Bptr + (size_t)(t + 1) * 8 * N);
        }
        #pragma unroll
        for (int kk = 0; kk < 8; kk++) {
            float4 a0 = *(const float4*)&As[buf][kk][ty * 8];
            float4 a1 = *(const float4*)&As[buf][kk][ty * 8 + 4];
            float4 b0 = *(const float4*)&Bs[buf][kk][tx * 8];
            float4 b1 = *(const float4*)&Bs[buf][kk][tx * 8 + 4];
            float af[8] = {a0.x, a0.y, a0.z, a0.w, a1.x, a1.y, a1.z, a1.w};
            float bf[8] = {b0.x, b0.y, b0.z, b0.w, b1.x, b1.y, b1.z, b1.w};
            #pragma unroll
            for (int i = 0; i < 8; i++)
                #pragma unroll
                for (int j = 0; j < 8; j++)
                    acc[i][j] = fmaf(af[i], bf[j], acc[i][j]);
        }
        buf ^= 1;
    }

    #pragma unroll
    for (int i = 0; i < 8; i++) {
        const int row = m0 + ty * 8 + i;
        float* cp = C + (size_t)row * N + n0 + tx * 8;
        const float* rp = RES ? (Rm + (size_t)row * N + n0 + tx * 8) : nullptr;
        #pragma unroll
        for (int j = 0; j < 8; j++) {
            float v = acc[i][j] + bias[n0 + tx * 8 + j];
            if (RELU) v = fmaxf(v, 0.f);
            if (RES)  v += rp[j];
            cp[j] = v;
        }
    }
}

// ---------------- blocked attention with online softmax --------------------
// grid: (S/64, B*H). 64 q-rows per block, loop over 16 k-blocks of 64.
#define APAD 65
__global__ void __launch_bounds__(256)
attn_kernel(const float* __restrict__ Q, const float* __restrict__ K,
            const float* __restrict__ V, const int* __restrict__ mask,
            float* __restrict__ O) {
    const int qb = blockIdx.x;           // 0..15
    const int bh = blockIdx.y;           // 0..63
    const int b  = bh >> 4;              // /H
    const int h  = bh & 15;              // %H

    extern __shared__ float sm[];
    float* qs = sm;                      // 64*65
    float* ks = qs + 64 * APAD;
    float* vs = ks + 64 * APAD;
    float* ss = vs + 64 * APAD;
    float* rowm = ss + 64 * APAD;        // 64
    float* rowl = rowm + 64;
    float* rsc  = rowl + 64;

    const int tid = threadIdx.x;
    const int tx = tid & 15;             // col group (4 cols)
    const int ty = tid >> 4;             // row group (4 rows)
    const size_t base = (size_t)b * Sd * Dd + h * DKd;

    for (int i = tid; i < 64 * 64; i += 256) {
        int r = i >> 6, c = i & 63;
        qs[r * APAD + c] = Q[base + (size_t)(qb * 64 + r) * Dd + c];
    }
    float acc[4][4];
    #pragma unroll
    for (int i = 0; i < 4; i++)
        #pragma unroll
        for (int j = 0; j < 4; j++) acc[i][j] = 0.f;
    if (tid < 64) { rowm[tid] = -1e30f; rowl[tid] = 0.f; }
    __syncthreads();

    for (int kb = 0; kb < Sd / 64; kb++) {
        for (int i = tid; i < 64 * 64; i += 256) {
            int r = i >> 6, c = i & 63;
            size_t g = base + (size_t)(kb * 64 + r) * Dd + c;
            ks[r * APAD + c] = K[g];
            vs[r * APAD + c] = V[g];
        }
        __syncthreads();

        // S = Q K^T
        float s[4][4];
        #pragma unroll
        for (int i = 0; i < 4; i++)
            #pragma unroll
            for (int j = 0; j < 4; j++) s[i][j] = 0.f;
        #pragma unroll 8
        for (int kk = 0; kk < 64; kk++) {
            float qf[4], kf[4];
            #pragma unroll
            for (int i = 0; i < 4; i++) qf[i] = qs[(ty * 4 + i) * APAD + kk];
            #pragma unroll
            for (int j = 0; j < 4; j++) kf[j] = ks[(tx * 4 + j) * APAD + kk];
            #pragma unroll
            for (int i = 0; i < 4; i++)
                #pragma unroll
                for (int j = 0; j < 4; j++)
                    s[i][j] = fmaf(qf[i], kf[j], s[i][j]);
        }
        #pragma unroll
        for (int j = 0; j < 4; j++) {
            int col = kb * 64 + tx * 4 + j;
            int mk = mask[b * Sd + col];
            #pragma unroll
            for (int i = 0; i < 4; i++) {
                float v = s[i][j] * 0.125f;          // 1/sqrt(64)
                if (mk == 0) v = -1e9f;
                ss[(ty * 4 + i) * APAD + tx * 4 + j] = v;
            }
        }
        __syncthreads();

        // online softmax per row (threads 0..63)
        if (tid < 64) {
            float m_old = rowm[tid];
            float mx = m_old;
            #pragma unroll 8
            for (int j = 0; j < 64; j++) mx = fmaxf(mx, ss[tid * APAD + j]);
            float sc = expf(m_old - mx);
            float l = rowl[tid] * sc;
            #pragma unroll 8
            for (int j = 0; j < 64; j++) {
                float p = expf(ss[tid * APAD + j] - mx);
                ss[tid * APAD + j] = p;
                l += p;
            }
            rowm[tid] = mx; rowl[tid] = l; rsc[tid] = sc;
        }
        __syncthreads();

        // rescale O and accumulate P @ V
        #pragma unroll
        for (int i = 0; i < 4; i++) {
            float sc = rsc[ty * 4 + i];
            #pragma unroll
            for (int j = 0; j < 4; j++) acc[i][j] *= sc;
        }
        #pragma unroll 8
        for (int kk = 0; kk < 64; kk++) {
            float pf[4], vf[4];
            #pragma unroll
            for (int i = 0; i < 4; i++) pf[i] = ss[(ty * 4 + i) * APAD + kk];
            #pragma unroll
            for (int j = 0; j < 4; j++) vf[j] = vs[kk * APAD + tx * 4 + j];
            #pragma unroll
            for (int i = 0; i < 4; i++)
                #pragma unroll
                for (int j = 0; j < 4; j++)
                    acc[i][j] = fmaf(pf[i], vf[j], acc[i][j]);
        }
        __syncthreads();
    }

    #pragma unroll
    for (int i = 0; i < 4; i++) {
        int r = qb * 64 + ty * 4 + i;
        float invl = 1.0f / rowl[ty * 4 + i];
        #pragma unroll
        for (int j = 0; j < 4; j++)
            O[(size_t)b * Sd * Dd + (size_t)r * Dd + h * DKd + tx * 4 + j] =
                acc[i][j] * invl;
    }
}

// ---------------- orchestration --------------------------------------------
extern "C" void kernel_launch(void* const* d_in, const int* in_sizes, int n_in,
                              void* d_out, int out_size) {
    const float* x      = (const float*)d_in[0];
    const int*   mask   = (const int*)  d_in[1];
    const float* wq     = (const float*)d_in[2];
    const float* bq     = (const float*)d_in[3];
    const float* wk     = (const float*)d_in[4];
    const float* bk     = (const float*)d_in[5];
    const float* wv     = (const float*)d_in[6];
    const float* bv     = (const float*)d_in[7];
    const float* wo     = (const float*)d_in[8];
    const float* bo     = (const float*)d_in[9];
    const float* w1     = (const float*)d_in[10];
    const float* b1     = (const float*)d_in[11];
    const float* w2     = (const float*)d_in[12];
    const float* b2     = (const float*)d_in[13];
    const float* alpha1 = (const float*)d_in[14];
    const float* beta1  = (const float*)d_in[15];
    const float* alpha2 = (const float*)d_in[16];
    const float* beta2  = (const float*)d_in[17];
    float* out = (float*)d_out;

    float *xn, *q, *k, *v, *ctx, *x2, *xn2, *ff;
    cudaGetSymbolAddress((void**)&xn,  g_xn);
    cudaGetSymbolAddress((void**)&q,   g_q);
    cudaGetSymbolAddress((void**)&k,   g_k);
    cudaGetSymbolAddress((void**)&v,   g_v);
    cudaGetSymbolAddress((void**)&ctx, g_ctx);
    cudaGetSymbolAddress((void**)&x2,  g_x2);
    cudaGetSymbolAddress((void**)&xn2, g_xn2);
    cudaGetSymbolAddress((void**)&ff,  g_ff);

    const int attn_smem = (4 * 64 * APAD + 3 * 64) * (int)sizeof(float);
    cudaFuncSetAttribute(attn_kernel,
                         cudaFuncAttributeMaxDynamicSharedMemorySize, attn_smem);

    // 1. LN1
    ln_kernel<<<Md, 256>>>(x, xn, alpha1, beta1);

    // 2. Q, K, V projections
    dim3 gP(Dd / 128, Md / 128);
    sgemm128<false, false><<<gP, 256>>>(xn, wq, bq, nullptr, q, Md, Dd, Dd);
    sgemm128<false, false><<<gP, 256>>>(xn, wk, bk, nullptr, k, Md, Dd, Dd);
    sgemm128<false, false><<<gP, 256>>>(xn, wv, bv, nullptr, v, Md, Dd, Dd);

    // 3. attention
    attn_kernel<<<dim3(Sd / 64, Bd * Hd), 256, attn_smem>>>(q, k, v, mask, ctx);

    // 4. O projection + residual
    sgemm128<false, true><<<gP, 256>>>(ctx, wo, bo, x, x2, Md, Dd, Dd);

    // 5. LN2
    ln_kernel<<<Md, 256>>>(x2, xn2, alpha2, beta2);

    // 6. FF1 + ReLU
    dim3 gF1(DFFd / 128, Md / 128);
    sgemm128<true, false><<<gF1, 256>>>(xn2, w1, b1, nullptr, ff, Md, DFFd, Dd);

    // 7. FF2 + residual -> output
    dim3 gF2(Dd / 128, Md / 128);
    sgemm128<false, true><<<gF2, 256>>>(ff, w2, b2, x2, out, Md, Dd, DFFd);
}

// round 4
// speedup vs baseline: 2.0283x; 2.0283x over previous
#include <cuda_runtime.h>
#include <cuda_bf16.h>
#include <math.h>
#include <stdint.h>

#define Bd 4
#define Sd 1024
#define Dd 1024
#define Hd 16
#define DKd 64
#define DFFd 4096
#define Md (Bd * Sd)   // 4096 rows

// ---------------- scratch (device globals; no runtime allocation) ----------
__device__ float g_q  [Md * Dd];
__device__ float g_k  [Md * Dd];
__device__ float g_v  [Md * Dd];
__device__ float g_x2 [Md * Dd];
__device__ __nv_bfloat16 g_xn_h [Md * Dd],  g_xn_l [Md * Dd];
__device__ __nv_bfloat16 g_xn2_h[Md * Dd],  g_xn2_l[Md * Dd];
__device__ __nv_bfloat16 g_ctx_h[Md * Dd],  g_ctx_l[Md * Dd];
__device__ __nv_bfloat16 g_wqT_h[Dd * Dd],  g_wqT_l[Dd * Dd];
__device__ __nv_bfloat16 g_wkT_h[Dd * Dd],  g_wkT_l[Dd * Dd];
__device__ __nv_bfloat16 g_wvT_h[Dd * Dd],  g_wvT_l[Dd * Dd];
__device__ __nv_bfloat16 g_woT_h[Dd * Dd],  g_woT_l[Dd * Dd];
__device__ __nv_bfloat16 g_w1T_h[DFFd * Dd], g_w1T_l[DFFd * Dd];
__device__ __nv_bfloat16 g_w2T_h[Dd * DFFd], g_w2T_l[Dd * DFFd];
__device__ __nv_bfloat16 g_ff_h [(size_t)Md * DFFd], g_ff_l[(size_t)Md * DFFd];

// ---------------- PTX helpers (all sm_80-compatible, no 'a' features) ------
__device__ __forceinline__ uint32_t smem_u32(const void* p) {
    uint32_t a;
    asm("{ .reg .u64 t; cvta.to.shared.u64 t, %1; cvt.u32.u64 %0, t; }"
        : "=r"(a) : "l"(p));
    return a;
}
__device__ __forceinline__ void cp16(uint32_t s, const void* g) {
    asm volatile("cp.async.cg.shared.global [%0], [%1], 16;" :: "r"(s), "l"(g));
}
__device__ __forceinline__ void cp_commit() {
    asm volatile("cp.async.commit_group;");
}
template <int N>
__device__ __forceinline__ void cp_wait() {
    asm volatile("cp.async.wait_group %0;" :: "n"(N));
}
__device__ __forceinline__ void ldm4(uint32_t* r, uint32_t a) {
    asm volatile("ldmatrix.sync.aligned.m8n8.x4.shared.b16 {%0,%1,%2,%3}, [%4];"
        : "=r"(r[0]), "=r"(r[1]), "=r"(r[2]), "=r"(r[3]) : "r"(a));
}
__device__ __forceinline__ void mma_bf16(float* d, const uint32_t* a,
                                         uint32_t b0, uint32_t b1) {
    asm volatile(
        "mma.sync.aligned.m16n8k16.row.col.f32.bf16.bf16.f32 "
        "{%0,%1,%2,%3}, {%4,%5,%6,%7}, {%8,%9}, {%0,%1,%2,%3};"
        : "+f"(d[0]), "+f"(d[1]), "+f"(d[2]), "+f"(d[3])
        : "r"(a[0]), "r"(a[1]), "r"(a[2]), "r"(a[3]), "r"(b0), "r"(b1));
}

// ---------------- LayerNorm (torch-style: ddof=1, eps on std) → bf16 hi/lo -
__global__ void ln_kernel(const float* __restrict__ X,
                          __nv_bfloat16* __restrict__ Yh,
                          __nv_bfloat16* __restrict__ Yl,
                          const float* __restrict__ alpha,
                          const float* __restrict__ beta) {
    __shared__ float red[256];
    __shared__ float s_mean, s_inv;
    const int row = blockIdx.x;
    const int tid = threadIdx.x;
    const float* x = X + (size_t)row * Dd;

    float4 xv = *(const float4*)(x + tid * 4);
    float s = xv.x + xv.y + xv.z + xv.w;
    red[tid] = s; __syncthreads();
    #pragma unroll
    for (int off = 128; off > 0; off >>= 1) {
        if (tid < off) red[tid] += red[tid + off];
        __syncthreads();
    }
    if (tid == 0) s_mean = red[0] * (1.0f / Dd);
    __syncthreads();
    const float mean = s_mean;
    float d0 = xv.x - mean, d1 = xv.y - mean, d2 = xv.z - mean, d3 = xv.w - mean;
    red[tid] = d0 * d0 + d1 * d1 + d2 * d2 + d3 * d3; __syncthreads();
    #pragma unroll
    for (int off = 128; off > 0; off >>= 1) {
        if (tid < off) red[tid] += red[tid + off];
        __syncthreads();
    }
    if (tid == 0) {
        float var = red[0] * (1.0f / (Dd - 1));
        s_inv = alpha[0] / (sqrtf(var) + 1e-6f);
    }
    __syncthreads();
    const float inv = s_inv;
    const float bt  = beta[0];
    float y[4] = {d0 * inv + bt, d1 * inv + bt, d2 * inv + bt, d3 * inv + bt};
    size_t o = (size_t)row * Dd + tid * 4;
    #pragma unroll
    for (int i = 0; i < 4; i++) {
        __nv_bfloat16 h = __float2bfloat16(y[i]);
        Yh[o + i] = h;
        Yl[o + i] = __float2bfloat16(y[i] - __bfloat162float(h));
    }
}

// ---------------- weight transpose + bf16 hi/lo split -----------------------
// in: f32 [R, C] row-major;  out: bf16 [C, R] (hi and lo)
__global__ void transpose_split(const float* __restrict__ in,
                                __nv_bfloat16* __restrict__ oh,
                                __nv_bfloat16* __restrict__ ol,
                                int R, int C) {
    __shared__ float tile[32][33];
    const int c = blockIdx.x * 32 + threadIdx.x;
    const int r0 = blockIdx.y * 32;
    #pragma unroll
    for (int i = 0; i < 4; i++)
        tile[threadIdx.y + i * 8][threadIdx.x] =
            in[(size_t)(r0 + threadIdx.y + i * 8) * C + c];
    __syncthreads();
    const int rr = r0 + threadIdx.x;
    #pragma unroll
    for (int i = 0; i < 4; i++) {
        const int oc = blockIdx.x * 32 + threadIdx.y + i * 8;
        float v = tile[threadIdx.x][threadIdx.y + i * 8];
        __nv_bfloat16 h = __float2bfloat16(v);
        size_t o = (size_t)oc * R + rr;
        oh[o] = h;
        ol[o] = __float2bfloat16(v - __bfloat162float(h));
    }
}

// ---------------- bf16x3 GEMM via mma.sync, 128x128 tile, BK=64, 2 stages --
// C[M,N] = (Ah+Al)[M,K] @ (Bh+Bl)[N,K]^T   (AlBl dropped)
// MODE 0: Cf = acc + bias
// MODE 1: Cf = acc + bias + Rm
// MODE 2: Ch/Cl = bf16_split(relu(acc + bias))
#define TILE_B 16384                      // one 128x64 bf16 tile
#define STAGE_B (4 * TILE_B)              // Ah, Al, Bh, Bl
#define GEMM_SMEM (2 * STAGE_B)           // 131072

__device__ __forceinline__ int st_off(int r, int c16) {
    return r * 128 + ((c16 ^ (r & 7)) << 4);   // swizzled byte offset in tile
}

template <int MODE>
__global__ void __launch_bounds__(256, 1)
mma_gemm(const __nv_bfloat16* __restrict__ Ah, const __nv_bfloat16* __restrict__ Al,
         const __nv_bfloat16* __restrict__ Bh, const __nv_bfloat16* __restrict__ Bl,
         const float* __restrict__ bias, const float* __restrict__ Rm,
         float* __restrict__ Cf,
         __nv_bfloat16* __restrict__ Ch, __nv_bfloat16* __restrict__ Cl,
         int M, int N, int K) {
    extern __shared__ char smem[];
    const uint32_t sb = smem_u32(smem);
    const int tid = threadIdx.x;
    const int wid = tid >> 5, lane = tid & 31;
    const int m0 = blockIdx.y * 128;
    const int n0 = blockIdx.x * 128;
    const int wm = (wid >> 2) * 64;       // warp row offset within tile
    const int wn = (wid & 3) * 32;        // warp col offset within tile

    float acc[4][4][4];
    #pragma unroll
    for (int a = 0; a < 4; a++)
        #pragma unroll
        for (int b = 0; b < 4; b++)
            #pragma unroll
            for (int c = 0; c < 4; c++) acc[a][b][c] = 0.f;

    const int nstg = K >> 6;

    auto load_stage = [&](int t, int s) {
        const int k0 = t << 6;
        #pragma unroll
        for (int i = 0; i < 4; i++) {
            const int chunk = tid + i * 256;          // 0..1023
            const int r = chunk >> 3, c = chunk & 7;
            const uint32_t so = sb + (uint32_t)s * STAGE_B + st_off(r, c);
            const size_t ga = (size_t)(m0 + r) * K + k0 + c * 8;
            const size_t gb = (size_t)(n0 + r) * K + k0 + c * 8;
            cp16(so + 0 * TILE_B, Ah + ga);
            cp16(so + 1 * TILE_B, Al + ga);
            cp16(so + 2 * TILE_B, Bh + gb);
            cp16(so + 3 * TILE_B, Bl + gb);
        }
        cp_commit();
    };

    load_stage(0, 0);

    const int lrow = lane & 15, lsel = lane >> 4;

    for (int t = 0; t < nstg; t++) {
        const int s = t & 1;
        if (t + 1 < nstg) { load_stage(t + 1, s ^ 1); cp_wait<1>(); }
        else              { cp_wait<0>(); }
        __syncthreads();

        const uint32_t stg = sb + (uint32_t)s * STAGE_B;
        #pragma unroll
        for (int kk = 0; kk < 4; kk++) {
            uint32_t ah[4][4], al[4][4], bh[2][4], bl[2][4];
            #pragma unroll
            for (int mt = 0; mt < 4; mt++) {
                const uint32_t ad = stg + st_off(wm + mt * 16 + lrow, kk * 2 + lsel);
                ldm4(ah[mt], ad);
                ldm4(al[mt], ad + TILE_B);
            }
            #pragma unroll
            for (int g = 0; g < 2; g++) {
                const uint32_t bd = stg + 2 * TILE_B +
                                    st_off(wn + g * 16 + lrow, kk * 2 + lsel);
                ldm4(bh[g], bd);
                ldm4(bl[g], bd + TILE_B);
            }
            #pragma unroll
            for (int mt = 0; mt < 4; mt++) {
                #pragma unroll
                for (int nt2 = 0; nt2 < 4; nt2++) {
                    const int g = nt2 >> 1, sel = nt2 & 1;
                    mma_bf16(acc[mt][nt2], ah[mt], bh[g][sel], bh[g][sel + 2]);
                    mma_bf16(acc[mt][nt2], ah[mt], bl[g][sel], bl[g][sel + 2]);
                    mma_bf16(acc[mt][nt2], al[mt], bh[g][sel], bh[g][sel + 2]);
                }
            }
        }
        __syncthreads();
    }

    // epilogue: c frag layout m16n8 -> (row lane/4 [+8], col (lane%4)*2 [+1])
    const int er = lane >> 2, ec = (lane & 3) * 2;
    #pragma unroll
    for (int mt = 0; mt < 4; mt++) {
        #pragma unroll
        for (int half = 0; half < 2; half++) {
            const int row = m0 + wm + mt * 16 + er + half * 8;
            #pragma unroll
            for (int nt2 = 0; nt2 < 4; nt2++) {
                const int col = n0 + wn + nt2 * 8 + ec;
                float v0 = acc[mt][nt2][half * 2 + 0] + bias[col];
                float v1 = acc[mt][nt2][half * 2 + 1] + bias[col + 1];
                const size_t o = (size_t)row * N + col;
                if (MODE == 2) {
                    v0 = fmaxf(v0, 0.f); v1 = fmaxf(v1, 0.f);
                    __nv_bfloat16 h0 = __float2bfloat16(v0);
                    __nv_bfloat16 h1 = __float2bfloat16(v1);
                    __nv_bfloat162 hp; hp.x = h0; hp.y = h1;
                    *(__nv_bfloat162*)(Ch + o) = hp;
                    __nv_bfloat162 lp;
                    lp.x = __float2bfloat16(v0 - __bfloat162float(h0));
                    lp.y = __float2bfloat16(v1 - __bfloat162float(h1));
                    *(__nv_bfloat162*)(Cl + o) = lp;
                } else {
                    if (MODE == 1) { v0 += Rm[o]; v1 += Rm[o + 1]; }
                    *(float2*)(Cf + o) = make_float2(v0, v1);
                }
            }
        }
    }
}

// ---------------- blocked attention with online softmax --------------------
#define APAD 65
__global__ void __launch_bounds__(256)
attn_kernel(const float* __restrict__ Q, const float* __restrict__ K,
            const float* __restrict__ V, const int* __restrict__ mask,
            __nv_bfloat16* __restrict__ Oh, __nv_bfloat16* __restrict__ Ol) {
    const int qb = blockIdx.x;
    const int bh = blockIdx.y;
    const int b  = bh >> 4;
    const int h  = bh & 15;

    extern __shared__ float sm[];
    float* qs = sm;
    float* ks = qs + 64 * APAD;
    float* vs = ks + 64 * APAD;
    float* ss = vs + 64 * APAD;
    float* rowm = ss + 64 * APAD;
    float* rowl = rowm + 64;
    float* rsc  = rowl + 64;

    const int tid = threadIdx.x;
    const int tx = tid & 15;
    const int ty = tid >> 4;
    const size_t base = (size_t)b * Sd * Dd + h * DKd;

    for (int i = tid; i < 64 * 64; i += 256) {
        int r = i >> 6, c = i & 63;
        qs[r * APAD + c] = Q[base + (size_t)(qb * 64 + r) * Dd + c];
    }
    float acc[4][4];
    #pragma unroll
    for (int i = 0; i < 4; i++)
        #pragma unroll
        for (int j = 0; j < 4; j++) acc[i][j] = 0.f;
    if (tid < 64) { rowm[tid] = -1e30f; rowl[tid] = 0.f; }
    __syncthreads();

    for (int kb = 0; kb < Sd / 64; kb++) {
        for (int i = tid; i < 64 * 64; i += 256) {
            int r = i >> 6, c = i & 63;
            size_t g = base + (size_t)(kb * 64 + r) * Dd + c;
            ks[r * APAD + c] = K[g];
            vs[r * APAD + c] = V[g];
        }
        __syncthreads();

        float s[4][4];
        #pragma unroll
        for (int i = 0; i < 4; i++)
            #pragma unroll
            for (int j = 0; j < 4; j++) s[i][j] = 0.f;
        #pragma unroll 8
        for (int kk = 0; kk < 64; kk++) {
            float qf[4], kf[4];
            #pragma unroll
            for (int i = 0; i < 4; i++) qf[i] = qs[(ty * 4 + i) * APAD + kk];
            #pragma unroll
            for (int j = 0; j < 4; j++) kf[j] = ks[(tx * 4 + j) * APAD + kk];
            #pragma unroll
            for (int i = 0; i < 4; i++)
                #pragma unroll
                for (int j = 0; j < 4; j++)
                    s[i][j] = fmaf(qf[i], kf[j], s[i][j]);
        }
        #pragma unroll
        for (int j = 0; j < 4; j++) {
            int col = kb * 64 + tx * 4 + j;
            int mk = mask[b * Sd + col];
            #pragma unroll
            for (int i = 0; i < 4; i++) {
                float v = s[i][j] * 0.125f;
                if (mk == 0) v = -1e9f;
                ss[(ty * 4 + i) * APAD + tx * 4 + j] = v;
            }
        }
        __syncthreads();

        if (tid < 64) {
            float m_old = rowm[tid];
            float mx = m_old;
            #pragma unroll 8
            for (int j = 0; j < 64; j++) mx = fmaxf(mx, ss[tid * APAD + j]);
            float sc = __expf(m_old - mx);
            float l = rowl[tid] * sc;
            #pragma unroll 8
            for (int j = 0; j < 64; j++) {
                float p = __expf(ss[tid * APAD + j] - mx);
                ss[tid * APAD + j] = p;
                l += p;
            }
            rowm[tid] = mx; rowl[tid] = l; rsc[tid] = sc;
        }
        __syncthreads();

        #pragma unroll
        for (int i = 0; i < 4; i++) {
            float sc = rsc[ty * 4 + i];
            #pragma unroll
            for (int j = 0; j < 4; j++) acc[i][j] *= sc;
        }
        #pragma unroll 8
        for (int kk = 0; kk < 64; kk++) {
            float pf[4], vf[4];
            #pragma unroll
            for (int i = 0; i < 4; i++) pf[i] = ss[(ty * 4 + i) * APAD + kk];
            #pragma unroll
            for (int j = 0; j < 4; j++) vf[j] = vs[kk * APAD + tx * 4 + j];
            #pragma unroll
            for (int i = 0; i < 4; i++)
                #pragma unroll
                for (int j = 0; j < 4; j++)
                    acc[i][j] = fmaf(pf[i], vf[j], acc[i][j]);
        }
        __syncthreads();
    }

    #pragma unroll
    for (int i = 0; i < 4; i++) {
        int r = qb * 64 + ty * 4 + i;
        float invl = 1.0f / rowl[ty * 4 + i];
        #pragma unroll
        for (int j = 0; j < 4; j++) {
            float v = acc[i][j] * invl;
            size_t o = (size_t)b * Sd * Dd + (size_t)r * Dd + h * DKd + tx * 4 + j;
            __nv_bfloat16 hh = __float2bfloat16(v);
            Oh[o] = hh;
            Ol[o] = __float2bfloat16(v - __bfloat162float(hh));
        }
    }
}

// ---------------- orchestration --------------------------------------------
extern "C" void kernel_launch(void* const* d_in, const int* in_sizes, int n_in,
                              void* d_out, int out_size) {
    const float* x      = (const float*)d_in[0];
    const int*   mask   = (const int*)  d_in[1];
    const float* wq     = (const float*)d_in[2];
    const float* bq     = (const float*)d_in[3];
    const float* wk     = (const float*)d_in[4];
    const float* bk     = (const float*)d_in[5];
    const float* wv     = (const float*)d_in[6];
    const float* bv     = (const float*)d_in[7];
    const float* wo     = (const float*)d_in[8];
    const float* bo     = (const float*)d_in[9];
    const float* w1     = (const float*)d_in[10];
    const float* b1     = (const float*)d_in[11];
    const float* w2     = (const float*)d_in[12];
    const float* b2     = (const float*)d_in[13];
    const float* alpha1 = (const float*)d_in[14];
    const float* beta1  = (const float*)d_in[15];
    const float* alpha2 = (const float*)d_in[16];
    const float* beta2  = (const float*)d_in[17];
    float* out = (float*)d_out;

    float *q, *k, *v, *x2;
    __nv_bfloat16 *xn_h, *xn_l, *xn2_h, *xn2_l, *ctx_h, *ctx_l;
    __nv_bfloat16 *wqT_h, *wqT_l, *wkT_h, *wkT_l, *wvT_h, *wvT_l, *woT_h, *woT_l;
    __nv_bfloat16 *w1T_h, *w1T_l, *w2T_h, *w2T_l, *ff_h, *ff_l;
    cudaGetSymbolAddress((void**)&q, g_q);
    cudaGetSymbolAddress((void**)&k, g_k);
    cudaGetSymbolAddress((void**)&v, g_v);
    cudaGetSymbolAddress((void**)&x2, g_x2);
    cudaGetSymbolAddress((void**)&xn_h, g_xn_h);   cudaGetSymbolAddress((void**)&xn_l, g_xn_l);
    cudaGetSymbolAddress((void**)&xn2_h, g_xn2_h); cudaGetSymbolAddress((void**)&xn2_l, g_xn2_l);
    cudaGetSymbolAddress((void**)&ctx_h, g_ctx_h); cudaGetSymbolAddress((void**)&ctx_l, g_ctx_l);
    cudaGetSymbolAddress((void**)&wqT_h, g_wqT_h); cudaGetSymbolAddress((void**)&wqT_l, g_wqT_l);
    cudaGetSymbolAddress((void**)&wkT_h, g_wkT_h); cudaGetSymbolAddress((void**)&wkT_l, g_wkT_l);
    cudaGetSymbolAddress((void**)&wvT_h, g_wvT_h); cudaGetSymbolAddress((void**)&wvT_l, g_wvT_l);
    cudaGetSymbolAddress((void**)&woT_h, g_woT_h); cudaGetSymbolAddress((void**)&woT_l, g_woT_l);
    cudaGetSymbolAddress((void**)&w1T_h, g_w1T_h); cudaGetSymbolAddress((void**)&w1T_l, g_w1T_l);
    cudaGetSymbolAddress((void**)&w2T_h, g_w2T_h); cudaGetSymbolAddress((void**)&w2T_l, g_w2T_l);
    cudaGetSymbolAddress((void**)&ff_h, g_ff_h);   cudaGetSymbolAddress((void**)&ff_l, g_ff_l);

    cudaFuncSetAttribute(mma_gemm<0>, cudaFuncAttributeMaxDynamicSharedMemorySize, GEMM_SMEM);
    cudaFuncSetAttribute(mma_gemm<1>, cudaFuncAttributeMaxDynamicSharedMemorySize, GEMM_SMEM);
    cudaFuncSetAttribute(mma_gemm<2>, cudaFuncAttributeMaxDynamicSharedMemorySize, GEMM_SMEM);
    const int attn_smem = (4 * 64 * APAD + 3 * 64) * (int)sizeof(float);
    cudaFuncSetAttribute(attn_kernel, cudaFuncAttributeMaxDynamicSharedMemorySize, attn_smem);

    // 0. weight transpose + bf16 split
    dim3 tb(32, 8);
    transpose_split<<<dim3(Dd / 32, Dd / 32), tb>>>(wq, wqT_h, wqT_l, Dd, Dd);
    transpose_split<<<dim3(Dd / 32, Dd / 32), tb>>>(wk, wkT_h, wkT_l, Dd, Dd);
    transpose_split<<<dim3(Dd / 32, Dd / 32), tb>>>(wv, wvT_h, wvT_l, Dd, Dd);
    transpose_split<<<dim3(Dd / 32, Dd / 32), tb>>>(wo, woT_h, woT_l, Dd, Dd);
    transpose_split<<<dim3(DFFd / 32, Dd / 32), tb>>>(w1, w1T_h, w1T_l, Dd, DFFd);
    transpose_split<<<dim3(Dd / 32, DFFd / 32), tb>>>(w2, w2T_h, w2T_l, DFFd, Dd);

    // 1. LN1 -> xn (hi/lo)
    ln_kernel<<<Md, 256>>>(x, xn_h, xn_l, alpha1, beta1);

    // 2. Q, K, V projections (bf16x3 tensor mma)
    dim3 gP(Dd / 128, Md / 128);
    mma_gemm<0><<<gP, 256, GEMM_SMEM>>>(xn_h, xn_l, wqT_h, wqT_l, bq, nullptr, q, nullptr, nullptr, Md, Dd, Dd);
    mma_gemm<0><<<gP, 256, GEMM_SMEM>>>(xn_h, xn_l, wkT_h, wkT_l, bk, nullptr, k, nullptr, nullptr, Md, Dd, Dd);
    mma_gemm<0><<<gP, 256, GEMM_SMEM>>>(xn_h, xn_l, wvT_h, wvT_l, bv, nullptr, v, nullptr, nullptr, Md, Dd, Dd);

    // 3. attention -> ctx (hi/lo)
    attn_kernel<<<dim3(Sd / 64, Bd * Hd), 256, attn_smem>>>(q, k, v, mask, ctx_h, ctx_l);

    // 4. O projection + residual -> x2 (f32)
    mma_gemm<1><<<gP, 256, GEMM_SMEM>>>(ctx_h, ctx_l, woT_h, woT_l, bo, x, x2, nullptr, nullptr, Md, Dd, Dd);

    // 5. LN2 -> xn2 (hi/lo)
    ln_kernel<<<Md, 256>>>(x2, xn2_h, xn2_l, alpha2, beta2);

    // 6. FF1 + ReLU -> ff (hi/lo)
    dim3 gF1(DFFd / 128, Md / 128);
    mma_gemm<2><<<gF1, 256, GEMM_SMEM>>>(xn2_h, xn2_l, w1T_h, w1T_l, b1, nullptr, nullptr, ff_h, ff_l, Md, DFFd, Dd);

    // 7. FF2 + residual -> out (f32)
    dim3 gF2(Dd / 128, Md / 128);
    mma_gemm<1><<<gF2, 256, GEMM_SMEM>>>(ff_h, ff_l, w2T_h, w2T_l, b2, x2, out, nullptr, nullptr, Md, Dd, DFFd);
}

// round 5
// speedup vs baseline: 2.6803x; 1.3214x over previous
#include <cuda_runtime.h>
#include <cuda_bf16.h>
#include <math.h>
#include <stdint.h>
#include <string.h>

#define Bd 4
#define Sd 1024
#define Dd 1024
#define Hd 16
#define DKd 64
#define DFFd 4096
#define Md (Bd * Sd)   // 4096 rows

// ---------------- scratch (device globals; no runtime allocation) ----------
__device__ float g_x2 [Md * Dd];
__device__ __nv_bfloat16 g_xn_h [Md * Dd],  g_xn_l [Md * Dd];
__device__ __nv_bfloat16 g_xn2_h[Md * Dd],  g_xn2_l[Md * Dd];
__device__ __nv_bfloat16 g_ctx_h[Md * Dd],  g_ctx_l[Md * Dd];
__device__ __nv_bfloat16 g_qh[Md * Dd], g_ql[Md * Dd];
__device__ __nv_bfloat16 g_kh[Md * Dd], g_kl[Md * Dd];
__device__ __nv_bfloat16 g_vh[Md * Dd], g_vl[Md * Dd];
__device__ __nv_bfloat16 g_wqT_h[Dd * Dd],  g_wqT_l[Dd * Dd];
__device__ __nv_bfloat16 g_wkT_h[Dd * Dd],  g_wkT_l[Dd * Dd];
__device__ __nv_bfloat16 g_wvT_h[Dd * Dd],  g_wvT_l[Dd * Dd];
__device__ __nv_bfloat16 g_woT_h[Dd * Dd],  g_woT_l[Dd * Dd];
__device__ __nv_bfloat16 g_w1T_h[DFFd * Dd], g_w1T_l[DFFd * Dd];
__device__ __nv_bfloat16 g_w2T_h[Dd * DFFd], g_w2T_l[Dd * DFFd];
__device__ __nv_bfloat16 g_ff_h [(size_t)Md * DFFd], g_ff_l[(size_t)Md * DFFd];

// ---------------- PTX helpers (sm_80-compatible) ----------------------------
__device__ __forceinline__ uint32_t smem_u32(const void* p) {
    uint32_t a;
    asm("{ .reg .u64 t; cvta.to.shared.u64 t, %1; cvt.u32.u64 %0, t; }"
        : "=r"(a) : "l"(p));
    return a;
}
__device__ __forceinline__ void cp16(uint32_t s, const void* g) {
    asm volatile("cp.async.cg.shared.global [%0], [%1], 16;" :: "r"(s), "l"(g));
}
__device__ __forceinline__ void cp_commit() {
    asm volatile("cp.async.commit_group;");
}
template <int N>
__device__ __forceinline__ void cp_wait() {
    asm volatile("cp.async.wait_group %0;" :: "n"(N));
}
__device__ __forceinline__ void ldm4(uint32_t* r, uint32_t a) {
    asm volatile("ldmatrix.sync.aligned.m8n8.x4.shared.b16 {%0,%1,%2,%3}, [%4];"
        : "=r"(r[0]), "=r"(r[1]), "=r"(r[2]), "=r"(r[3]) : "r"(a));
}
__device__ __forceinline__ void ldm4t(uint32_t* r, uint32_t a) {
    asm volatile("ldmatrix.sync.aligned.m8n8.x4.trans.shared.b16 {%0,%1,%2,%3}, [%4];"
        : "=r"(r[0]), "=r"(r[1]), "=r"(r[2]), "=r"(r[3]) : "r"(a));
}
__device__ __forceinline__ void mma_bf16(float* d, const uint32_t* a,
                                         uint32_t b0, uint32_t b1) {
    asm volatile(
        "mma.sync.aligned.m16n8k16.row.col.f32.bf16.bf16.f32 "
        "{%0,%1,%2,%3}, {%4,%5,%6,%7}, {%8,%9}, {%0,%1,%2,%3};"
        : "+f"(d[0]), "+f"(d[1]), "+f"(d[2]), "+f"(d[3])
        : "r"(a[0]), "r"(a[1]), "r"(a[2]), "r"(a[3]), "r"(b0), "r"(b1));
}
__device__ __forceinline__ uint32_t pack_bf2(float a, float b) {
    __nv_bfloat162 t;
    t.x = __float2bfloat16(a); t.y = __float2bfloat16(b);
    uint32_t u; memcpy(&u, &t, 4); return u;
}
__device__ __forceinline__ int st_off(int r, int c16) {
    return r * 128 + ((c16 ^ (r & 7)) << 4);   // swizzled byte offset (128B rows)
}

// ---------------- LayerNorm (torch-style: ddof=1, eps on std) → bf16 hi/lo -
__global__ void ln_kernel(const float* __restrict__ X,
                          __nv_bfloat16* __restrict__ Yh,
                          __nv_bfloat16* __restrict__ Yl,
                          const float* __restrict__ alpha,
                          const float* __restrict__ beta) {
    __shared__ float red[256];
    __shared__ float s_mean, s_inv;
    const int row = blockIdx.x;
    const int tid = threadIdx.x;
    const float* x = X + (size_t)row * Dd;

    float4 xv = *(const float4*)(x + tid * 4);
    float s = xv.x + xv.y + xv.z + xv.w;
    red[tid] = s; __syncthreads();
    #pragma unroll
    for (int off = 128; off > 0; off >>= 1) {
        if (tid < off) red[tid] += red[tid + off];
        __syncthreads();
    }
    if (tid == 0) s_mean = red[0] * (1.0f / Dd);
    __syncthreads();
    const float mean = s_mean;
    float d0 = xv.x - mean, d1 = xv.y - mean, d2 = xv.z - mean, d3 = xv.w - mean;
    red[tid] = d0 * d0 + d1 * d1 + d2 * d2 + d3 * d3; __syncthreads();
    #pragma unroll
    for (int off = 128; off > 0; off >>= 1) {
        if (tid < off) red[tid] += red[tid + off];
        __syncthreads();
    }
    if (tid == 0) {
        float var = red[0] * (1.0f / (Dd - 1));
        s_inv = alpha[0] / (sqrtf(var) + 1e-6f);
    }
    __syncthreads();
    const float inv = s_inv;
    const float bt  = beta[0];
    float y[4] = {d0 * inv + bt, d1 * inv + bt, d2 * inv + bt, d3 * inv + bt};
    size_t o = (size_t)row * Dd + tid * 4;
    #pragma unroll
    for (int i = 0; i < 4; i++) {
        __nv_bfloat16 h = __float2bfloat16(y[i]);
        Yh[o + i] = h;
        Yl[o + i] = __float2bfloat16(y[i] - __bfloat162float(h));
    }
}

// ---------------- weight transpose + bf16 hi/lo split -----------------------
__global__ void transpose_split(const float* __restrict__ in,
                                __nv_bfloat16* __restrict__ oh,
                                __nv_bfloat16* __restrict__ ol,
                                int R, int C) {
    __shared__ float tile[32][33];
    const int c = blockIdx.x * 32 + threadIdx.x;
    const int r0 = blockIdx.y * 32;
    #pragma unroll
    for (int i = 0; i < 4; i++)
        tile[threadIdx.y + i * 8][threadIdx.x] =
            in[(size_t)(r0 + threadIdx.y + i * 8) * C + c];
    __syncthreads();
    const int rr = r0 + threadIdx.x;
    #pragma unroll
    for (int i = 0; i < 4; i++) {
        const int oc = blockIdx.x * 32 + threadIdx.y + i * 8;
        float v = tile[threadIdx.x][threadIdx.y + i * 8];
        __nv_bfloat16 h = __float2bfloat16(v);
        size_t o = (size_t)oc * R + rr;
        oh[o] = h;
        ol[o] = __float2bfloat16(v - __bfloat162float(h));
    }
}

// ---------------- bf16x3 GEMM via mma.sync, 128x128 tile, BK=64, 2 stages --
// MODE 0: Cf = acc + bias
// MODE 1: Cf = acc + bias + Rm
// MODE 2: Ch/Cl = bf16_split(relu(acc + bias))
// MODE 3: Ch/Cl = bf16_split(acc + bias)
#define TILE_B 16384
#define STAGE_B (4 * TILE_B)
#define GEMM_SMEM (2 * STAGE_B)

template <int MODE>
__global__ void __launch_bounds__(256, 1)
mma_gemm(const __nv_bfloat16* __restrict__ Ah, const __nv_bfloat16* __restrict__ Al,
         const __nv_bfloat16* __restrict__ Bh, const __nv_bfloat16* __restrict__ Bl,
         const float* __restrict__ bias, const float* __restrict__ Rm,
         float* __restrict__ Cf,
         __nv_bfloat16* __restrict__ Ch, __nv_bfloat16* __restrict__ Cl,
         int M, int N, int K) {
    extern __shared__ char smem[];
    const uint32_t sb = smem_u32(smem);
    const int tid = threadIdx.x;
    const int wid = tid >> 5, lane = tid & 31;
    const int m0 = blockIdx.y * 128;
    const int n0 = blockIdx.x * 128;
    const int wm = (wid >> 2) * 64;
    const int wn = (wid & 3) * 32;

    float acc[4][4][4];
    #pragma unroll
    for (int a = 0; a < 4; a++)
        #pragma unroll
        for (int b = 0; b < 4; b++)
            #pragma unroll
            for (int c = 0; c < 4; c++) acc[a][b][c] = 0.f;

    const int nstg = K >> 6;

    auto load_stage = [&](int t, int s) {
        const int k0 = t << 6;
        #pragma unroll
        for (int i = 0; i < 4; i++) {
            const int chunk = tid + i * 256;
            const int r = chunk >> 3, c = chunk & 7;
            const uint32_t so = sb + (uint32_t)s * STAGE_B + st_off(r, c);
            const size_t ga = (size_t)(m0 + r) * K + k0 + c * 8;
            const size_t gb = (size_t)(n0 + r) * K + k0 + c * 8;
            cp16(so + 0 * TILE_B, Ah + ga);
            cp16(so + 1 * TILE_B, Al + ga);
            cp16(so + 2 * TILE_B, Bh + gb);
            cp16(so + 3 * TILE_B, Bl + gb);
        }
        cp_commit();
    };

    load_stage(0, 0);

    const int lrow = lane & 15, lsel = lane >> 4;

    for (int t = 0; t < nstg; t++) {
        const int s = t & 1;
        if (t + 1 < nstg) { load_stage(t + 1, s ^ 1); cp_wait<1>(); }
        else              { cp_wait<0>(); }
        __syncthreads();

        const uint32_t stg = sb + (uint32_t)s * STAGE_B;
        #pragma unroll
        for (int kk = 0; kk < 4; kk++) {
            uint32_t ah[4][4], al[4][4], bh[2][4], bl[2][4];
            #pragma unroll
            for (int mt = 0; mt < 4; mt++) {
                const uint32_t ad = stg + st_off(wm + mt * 16 + lrow, kk * 2 + lsel);
                ldm4(ah[mt], ad);
                ldm4(al[mt], ad + TILE_B);
            }
            #pragma unroll
            for (int g = 0; g < 2; g++) {
                const uint32_t bd = stg + 2 * TILE_B +
                                    st_off(wn + g * 16 + lrow, kk * 2 + lsel);
                ldm4(bh[g], bd);
                ldm4(bl[g], bd + TILE_B);
            }
            #pragma unroll
            for (int mt = 0; mt < 4; mt++) {
                #pragma unroll
                for (int nt2 = 0; nt2 < 4; nt2++) {
                    const int g = nt2 >> 1, sel = nt2 & 1;
                    mma_bf16(acc[mt][nt2], ah[mt], bh[g][sel], bh[g][sel + 2]);
                    mma_bf16(acc[mt][nt2], ah[mt], bl[g][sel], bl[g][sel + 2]);
                    mma_bf16(acc[mt][nt2], al[mt], bh[g][sel], bh[g][sel + 2]);
                }
            }
        }
        __syncthreads();
    }

    const int er = lane >> 2, ec = (lane & 3) * 2;
    #pragma unroll
    for (int mt = 0; mt < 4; mt++) {
        #pragma unroll
        for (int half = 0; half < 2; half++) {
            const int row = m0 + wm + mt * 16 + er + half * 8;
            #pragma unroll
            for (int nt2 = 0; nt2 < 4; nt2++) {
                const int col = n0 + wn + nt2 * 8 + ec;
                float v0 = acc[mt][nt2][half * 2 + 0] + bias[col];
                float v1 = acc[mt][nt2][half * 2 + 1] + bias[col + 1];
                const size_t o = (size_t)row * N + col;
                if (MODE >= 2) {
                    if (MODE == 2) { v0 = fmaxf(v0, 0.f); v1 = fmaxf(v1, 0.f); }
                    __nv_bfloat16 h0 = __float2bfloat16(v0);
                    __nv_bfloat16 h1 = __float2bfloat16(v1);
                    __nv_bfloat162 hp; hp.x = h0; hp.y = h1;
                    *(__nv_bfloat162*)(Ch + o) = hp;
                    __nv_bfloat162 lp;
                    lp.x = __float2bfloat16(v0 - __bfloat162float(h0));
                    lp.y = __float2bfloat16(v1 - __bfloat162float(h1));
                    *(__nv_bfloat162*)(Cl + o) = lp;
                } else {
                    if (MODE == 1) { v0 += Rm[o]; v1 += Rm[o + 1]; }
                    *(float2*)(Cf + o) = make_float2(v0, v1);
                }
            }
        }
    }
}

// ---------------- tensor-core flash attention (bf16x3 QK and PV) ------------
// grid (S/128, B*H), 256 threads (8 warps x m16). kv blocks of 64, 2 stages.
#define AQ_B  (128 * 128)            // Q tile bytes (128 rows x 128B)
#define AKV_B (64 * 128)             // KV tile bytes
#define AT_SMEM (2 * AQ_B + 2 * 4 * AKV_B + Sd * 4)

__global__ void __launch_bounds__(256, 1)
attn_mma(const __nv_bfloat16* __restrict__ Qh, const __nv_bfloat16* __restrict__ Ql,
         const __nv_bfloat16* __restrict__ Kh, const __nv_bfloat16* __restrict__ Kl,
         const __nv_bfloat16* __restrict__ Vh, const __nv_bfloat16* __restrict__ Vl,
         const int* __restrict__ mask,
         __nv_bfloat16* __restrict__ Oh, __nv_bfloat16* __restrict__ Ol) {
    extern __shared__ char smem[];
    const uint32_t sb = smem_u32(smem);
    const uint32_t sQh = sb, sQl = sb + AQ_B;
    int* smask = (int*)(smem + 2 * AQ_B + 2 * 4 * AKV_B);

    const int tid = threadIdx.x;
    const int wid = tid >> 5, lane = tid & 31;
    const int lrow = lane & 15, lsel = lane >> 4;
    const int lam = lane & 3, ldv = lane >> 2;

    const int qb = blockIdx.x, bh = blockIdx.y;
    const int b = bh >> 4, h = bh & 15;
    const size_t base = (size_t)b * Sd * Dd + h * DKd;
    const int qrow0 = qb * 128;

    // Q tile (hi/lo) into smem
    #pragma unroll
    for (int i = 0; i < 4; i++) {
        const int chunk = tid + i * 256;          // 0..1023
        const int r = chunk >> 3, c = chunk & 7;
        const size_t g = base + (size_t)(qrow0 + r) * Dd + c * 8;
        cp16(sQh + st_off(r, c), Qh + g);
        cp16(sQl + st_off(r, c), Ql + g);
    }
    // mask row for this batch
    for (int i = tid; i < Sd; i += 256) smask[i] = mask[b * Sd + i];

    auto load_kv = [&](int kb, int s) {
        const uint32_t st = sb + 2 * AQ_B + (uint32_t)s * 4 * AKV_B;
        #pragma unroll
        for (int i = 0; i < 2; i++) {
            const int chunk = tid + i * 256;      // 0..511
            const int r = chunk >> 3, c = chunk & 7;
            const uint32_t so = st_off(r, c);
            const size_t g = base + (size_t)(kb * 64 + r) * Dd + c * 8;
            cp16(st + 0 * AKV_B + so, Kh + g);
            cp16(st + 1 * AKV_B + so, Kl + g);
            cp16(st + 2 * AKV_B + so, Vh + g);
            cp16(st + 3 * AKV_B + so, Vl + g);
        }
    };

    load_kv(0, 0);
    cp_commit();

    float O[8][4];
    #pragma unroll
    for (int j = 0; j < 8; j++)
        #pragma unroll
        for (int c = 0; c < 4; c++) O[j][c] = 0.f;
    float m0r = -1e30f, m1r = -1e30f, l0r = 0.f, l1r = 0.f;

    const int NKB = Sd / 64;
    for (int kb = 0; kb < NKB; kb++) {
        const int s = kb & 1;
        if (kb + 1 < NKB) { load_kv(kb + 1, s ^ 1); cp_commit(); cp_wait<1>(); }
        else              { cp_wait<0>(); }
        __syncthreads();

        const uint32_t stK = sb + 2 * AQ_B + (uint32_t)s * 4 * AKV_B;
        const uint32_t stV = stK + 2 * AKV_B;

        // ---- S = Q K^T (bf16x3) ----
        float Sc[8][4];
        #pragma unroll
        for (int j = 0; j < 8; j++)
            #pragma unroll
            for (int c = 0; c < 4; c++) Sc[j][c] = 0.f;
        #pragma unroll
        for (int kk = 0; kk < 4; kk++) {
            uint32_t qh[4], ql[4], kh[4][4], kl[4][4];
            const uint32_t qa = sQh + st_off(wid * 16 + lrow, kk * 2 + lsel);
            ldm4(qh, qa);
            ldm4(ql, qa + AQ_B);
            #pragma unroll
            for (int g = 0; g < 4; g++) {
                const uint32_t kd = stK + st_off(g * 16 + lrow, kk * 2 + lsel);
                ldm4(kh[g], kd);
                ldm4(kl[g], kd + AKV_B);
            }
            #pragma unroll
            for (int j = 0; j < 8; j++) {
                const int g = j >> 1, sel = j & 1;
                mma_bf16(Sc[j], qh, kh[g][sel], kh[g][sel + 2]);
                mma_bf16(Sc[j], qh, kl[g][sel], kl[g][sel + 2]);
                mma_bf16(Sc[j], ql, kh[g][sel], kh[g][sel + 2]);
            }
        }

        // ---- scale + mask ----
        #pragma unroll
        for (int j = 0; j < 8; j++) {
            const int col = kb * 64 + j * 8 + lam * 2;
            const int mk0 = smask[col], mk1 = smask[col + 1];
            #pragma unroll
            for (int c = 0; c < 4; c++) Sc[j][c] *= 0.125f;
            if (mk0 == 0) { Sc[j][0] = -1e9f; Sc[j][2] = -1e9f; }
            if (mk1 == 0) { Sc[j][1] = -1e9f; Sc[j][3] = -1e9f; }
        }

        // ---- online softmax (rows ldv, ldv+8 of this warp's m16) ----
        float mx0 = -1e30f, mx1 = -1e30f;
        #pragma unroll
        for (int j = 0; j < 8; j++) {
            mx0 = fmaxf(mx0, fmaxf(Sc[j][0], Sc[j][1]));
            mx1 = fmaxf(mx1, fmaxf(Sc[j][2], Sc[j][3]));
        }
        mx0 = fmaxf(mx0, __shfl_xor_sync(0xffffffffu, mx0, 1));
        mx0 = fmaxf(mx0, __shfl_xor_sync(0xffffffffu, mx0, 2));
        mx1 = fmaxf(mx1, __shfl_xor_sync(0xffffffffu, mx1, 1));
        mx1 = fmaxf(mx1, __shfl_xor_sync(0xffffffffu, mx1, 2));
        const float nm0 = fmaxf(m0r, mx0), nm1 = fmaxf(m1r, mx1);
        const float sf0 = __expf(m0r - nm0), sf1 = __expf(m1r - nm1);
        m0r = nm0; m1r = nm1;
        l0r *= sf0; l1r *= sf1;

        uint32_t pah[4][4], pal[4][4];
        #pragma unroll
        for (int j = 0; j < 8; j++) {
            float p0 = __expf(Sc[j][0] - nm0);
            float p1 = __expf(Sc[j][1] - nm0);
            float p2 = __expf(Sc[j][2] - nm1);
            float p3 = __expf(Sc[j][3] - nm1);
            l0r += p0 + p1; l1r += p2 + p3;
            const int t = j >> 1, hi = j & 1;      // k16 tile, k-half
            const uint32_t h01 = pack_bf2(p0, p1);
            const uint32_t h23 = pack_bf2(p2, p3);
            pah[t][hi * 2 + 0] = h01;
            pah[t][hi * 2 + 1] = h23;
            __nv_bfloat162 b01, b23;
            memcpy(&b01, &h01, 4); memcpy(&b23, &h23, 4);
            pal[t][hi * 2 + 0] = pack_bf2(p0 - __bfloat162float(b01.x),
                                          p1 - __bfloat162float(b01.y));
            pal[t][hi * 2 + 1] = pack_bf2(p2 - __bfloat162float(b23.x),
                                          p3 - __bfloat162float(b23.y));
        }

        // ---- rescale O ----
        #pragma unroll
        for (int j = 0; j < 8; j++) {
            O[j][0] *= sf0; O[j][1] *= sf0;
            O[j][2] *= sf1; O[j][3] *= sf1;
        }

        // ---- O += P V (bf16x3) ----
        #pragma unroll
        for (int t = 0; t < 4; t++) {
            #pragma unroll
            for (int jo = 0; jo < 4; jo++) {
                uint32_t vh[4], vl[4];
                const uint32_t vd = stV + st_off(t * 16 + lrow, jo * 2 + lsel);
                ldm4t(vh, vd);
                ldm4t(vl, vd + AKV_B);
                mma_bf16(O[jo * 2 + 0], pah[t], vh[0], vh[1]);
                mma_bf16(O[jo * 2 + 1], pah[t], vh[2], vh[3]);
                mma_bf16(O[jo * 2 + 0], pah[t], vl[0], vl[1]);
                mma_bf16(O[jo * 2 + 1], pah[t], vl[2], vl[3]);
                mma_bf16(O[jo * 2 + 0], pal[t], vh[0], vh[1]);
                mma_bf16(O[jo * 2 + 1], pal[t], vh[2], vh[3]);
            }
        }
        __syncthreads();
    }

    // full row sums across quad
    l0r += __shfl_xor_sync(0xffffffffu, l0r, 1);
    l0r += __shfl_xor_sync(0xffffffffu, l0r, 2);
    l1r += __shfl_xor_sync(0xffffffffu, l1r, 1);
    l1r += __shfl_xor_sync(0xffffffffu, l1r, 2);
    const float inv0 = 1.0f / l0r, inv1 = 1.0f / l1r;

    const int row0 = qrow0 + wid * 16 + ldv;
    #pragma unroll
    for (int jn = 0; jn < 8; jn++) {
        const int col = h * DKd + jn * 8 + lam * 2;
        #pragma unroll
        for (int half = 0; half < 2; half++) {
            const float inv = half ? inv1 : inv0;
            const float v0 = O[jn][half * 2 + 0] * inv;
            const float v1 = O[jn][half * 2 + 1] * inv;
            const size_t o = (size_t)b * Sd * Dd +
                             (size_t)(row0 + half * 8) * Dd + col;
            __nv_bfloat16 h0 = __float2bfloat16(v0);
            __nv_bfloat16 h1 = __float2bfloat16(v1);
            __nv_bfloat162 hp; hp.x = h0; hp.y = h1;
            *(__nv_bfloat162*)(Oh + o) = hp;
            __nv_bfloat162 lp;
            lp.x = __float2bfloat16(v0 - __bfloat162float(h0));
            lp.y = __float2bfloat16(v1 - __bfloat162float(h1));
            *(__nv_bfloat162*)(Ol + o) = lp;
        }
    }
}

// ---------------- orchestration --------------------------------------------
extern "C" void kernel_launch(void* const* d_in, const int* in_sizes, int n_in,
                              void* d_out, int out_size) {
    const float* x      = (const float*)d_in[0];
    const int*   mask   = (const int*)  d_in[1];
    const float* wq     = (const float*)d_in[2];
    const float* bq     = (const float*)d_in[3];
    const float* wk     = (const float*)d_in[4];
    const float* bk     = (const float*)d_in[5];
    const float* wv     = (const float*)d_in[6];
    const float* bv     = (const float*)d_in[7];
    const float* wo     = (const float*)d_in[8];
    const float* bo     = (const float*)d_in[9];
    const float* w1     = (const float*)d_in[10];
    const float* b1     = (const float*)d_in[11];
    const float* w2     = (const float*)d_in[12];
    const float* b2     = (const float*)d_in[13];
    const float* alpha1 = (const float*)d_in[14];
    const float* beta1  = (const float*)d_in[15];
    const float* alpha2 = (const float*)d_in[16];
    const float* beta2  = (const float*)d_in[17];
    float* out = (float*)d_out;

    float *x2;
    __nv_bfloat16 *xn_h, *xn_l, *xn2_h, *xn2_l, *ctx_h, *ctx_l;
    __nv_bfloat16 *qh, *ql, *kh, *kl, *vh, *vl;
    __nv_bfloat16 *wqT_h, *wqT_l, *wkT_h, *wkT_l, *wvT_h, *wvT_l, *woT_h, *woT_l;
    __nv_bfloat16 *w1T_h, *w1T_l, *w2T_h, *w2T_l, *ff_h, *ff_l;
    cudaGetSymbolAddress((void**)&x2, g_x2);
    cudaGetSymbolAddress((void**)&xn_h, g_xn_h);   cudaGetSymbolAddress((void**)&xn_l, g_xn_l);
    cudaGetSymbolAddress((void**)&xn2_h, g_xn2_h); cudaGetSymbolAddress((void**)&xn2_l, g_xn2_l);
    cudaGetSymbolAddress((void**)&ctx_h, g_ctx_h); cudaGetSymbolAddress((void**)&ctx_l, g_ctx_l);
    cudaGetSymbolAddress((void**)&qh, g_qh); cudaGetSymbolAddress((void**)&ql, g_ql);
    cudaGetSymbolAddress((void**)&kh, g_kh); cudaGetSymbolAddress((void**)&kl, g_kl);
    cudaGetSymbolAddress((void**)&vh, g_vh); cudaGetSymbolAddress((void**)&vl, g_vl);
    cudaGetSymbolAddress((void**)&wqT_h, g_wqT_h); cudaGetSymbolAddress((void**)&wqT_l, g_wqT_l);
    cudaGetSymbolAddress((void**)&wkT_h, g_wkT_h); cudaGetSymbolAddress((void**)&wkT_l, g_wkT_l);
    cudaGetSymbolAddress((void**)&wvT_h, g_wvT_h); cudaGetSymbolAddress((void**)&wvT_l, g_wvT_l);
    cudaGetSymbolAddress((void**)&woT_h, g_woT_h); cudaGetSymbolAddress((void**)&woT_l, g_woT_l);
    cudaGetSymbolAddress((void**)&w1T_h, g_w1T_h); cudaGetSymbolAddress((void**)&w1T_l, g_w1T_l);
    cudaGetSymbolAddress((void**)&w2T_h, g_w2T_h); cudaGetSymbolAddress((void**)&w2T_l, g_w2T_l);
    cudaGetSymbolAddress((void**)&ff_h, g_ff_h);   cudaGetSymbolAddress((void**)&ff_l, g_ff_l);

    cudaFuncSetAttribute(mma_gemm<1>, cudaFuncAttributeMaxDynamicSharedMemorySize, GEMM_SMEM);
    cudaFuncSetAttribute(mma_gemm<2>, cudaFuncAttributeMaxDynamicSharedMemorySize, GEMM_SMEM);
    cudaFuncSetAttribute(mma_gemm<3>, cudaFuncAttributeMaxDynamicSharedMemorySize, GEMM_SMEM);
    cudaFuncSetAttribute(attn_mma, cudaFuncAttributeMaxDynamicSharedMemorySize, AT_SMEM);

    // 0. weight transpose + bf16 split
    dim3 tb(32, 8);
    transpose_split<<<dim3(Dd / 32, Dd / 32), tb>>>(wq, wqT_h, wqT_l, Dd, Dd);
    transpose_split<<<dim3(Dd / 32, Dd / 32), tb>>>(wk, wkT_h, wkT_l, Dd, Dd);
    transpose_split<<<dim3(Dd / 32, Dd / 32), tb>>>(wv, wvT_h, wvT_l, Dd, Dd);
    transpose_split<<<dim3(Dd / 32, Dd / 32), tb>>>(wo, woT_h, woT_l, Dd, Dd);
    transpose_split<<<dim3(DFFd / 32, Dd / 32), tb>>>(w1, w1T_h, w1T_l, Dd, DFFd);
    transpose_split<<<dim3(Dd / 32, DFFd / 32), tb>>>(w2, w2T_h, w2T_l, DFFd, Dd);

    // 1. LN1 -> xn (hi/lo)
    ln_kernel<<<Md, 256>>>(x, xn_h, xn_l, alpha1, beta1);

    // 2. Q, K, V projections -> bf16 hi/lo
    dim3 gP(Dd / 128, Md / 128);
    mma_gemm<3><<<gP, 256, GEMM_SMEM>>>(xn_h, xn_l, wqT_h, wqT_l, bq, nullptr, nullptr, qh, ql, Md, Dd, Dd);
    mma_gemm<3><<<gP, 256, GEMM_SMEM>>>(xn_h, xn_l, wkT_h, wkT_l, bk, nullptr, nullptr, kh, kl, Md, Dd, Dd);
    mma_gemm<3><<<gP, 256, GEMM_SMEM>>>(xn_h, xn_l, wvT_h, wvT_l, bv, nullptr, nullptr, vh, vl, Md, Dd, Dd);

    // 3. tensor-core attention -> ctx (hi/lo)
    attn_mma<<<dim3(Sd / 128, Bd * Hd), 256, AT_SMEM>>>(qh, ql, kh, kl, vh, vl,
                                                        mask, ctx_h, ctx_l);

    // 4. O projection + residual -> x2 (f32)
    mma_gemm<1><<<gP, 256, GEMM_SMEM>>>(ctx_h, ctx_l, woT_h, woT_l, bo, x, x2, nullptr, nullptr, Md, Dd, Dd);

    // 5. LN2 -> xn2 (hi/lo)
    ln_kernel<<<Md, 256>>>(x2, xn2_h, xn2_l, alpha2, beta2);

    // 6. FF1 + ReLU -> ff (hi/lo)
    dim3 gF1(DFFd / 128, Md / 128);
    mma_gemm<2><<<gF1, 256, GEMM_SMEM>>>(xn2_h, xn2_l, w1T_h, w1T_l, b1, nullptr, nullptr, ff_h, ff_l, Md, DFFd, Dd);

    // 7. FF2 + residual -> out (f32)
    dim3 gF2(Dd / 128, Md / 128);
    mma_gemm<1><<<gF2, 256, GEMM_SMEM>>>(ff_h, ff_l, w2T_h, w2T_l, b2, x2, out, nullptr, nullptr, Md, Dd, DFFd);
}